// round 3
// baseline (speedup 1.0000x reference)
#include <cuda_runtime.h>
#include <cstdint>

// PatchEmbedder: B=8, P=1024, D=512, BUCKETS=65536, LS=(8,7,6)
//
// Inputs identified by element count (host side):
//   33554432 -> emb tables (3, appearance order = emb_1, emb_2, emb_3)
//   8192     -> patch_mask
//   65536    -> {ids_1, mask_1}   57344 -> {ids_2, mask_2}   49152 -> {ids_3, mask_3}
// Which member of each pair is ids vs mask, the mask element width (u8 / i32 /
// f32), the patch_mask width, and the ids stride (i32 vs i64) are all detected
// ON DEVICE by a probe kernel (graph-capturable, runs before the main kernel).

#define NPATCH (8 * 1024)
#define DV 128          // 512 floats = 128 float4 per embedding row
#define L1N 8
#define L2N 7
#define L3N 6
#define LTOT (L1N + L2N + L3N)  // 21
#define SAMPLES 256

// g_cfg layout:
//  [0..2] swap_k   : 1 if candidate A of pair k is the MASK (=> ids is B)
//  [3..5] stride_k : 1 (int32 ids) or 2 (int64 ids, read low word)
//  [6..8] mwidth_k : 1 (u8 mask) or 4 (i32/f32 mask; nonzero word == true)
//  [9]    pwidth   : patch_mask width, 1 or 4
__device__ int g_cfg[10];

__global__ void probe_kernel(const unsigned char* a1, const unsigned char* b1,
                             const unsigned char* a2, const unsigned char* b2,
                             const unsigned char* a3, const unsigned char* b3,
                             const unsigned char* pm)
{
    const int t = threadIdx.x;                       // 0..255
    const unsigned char* cand[6] = {a1, b1, a2, b2, a3, b3};
    const int n[6] = {65536, 65536, 57344, 57344, 49152, 49152};

    __shared__ int v_byte[7], v_w01[7], v_wf[7], v_odd[7];
    if (t < 7) { v_byte[t] = 0; v_w01[t] = 0; v_wf[t] = 0; v_odd[t] = 0; }
    __syncthreads();

    // Issue all sample loads first (independent -> one MLP batch).
    unsigned char bv[6]; int wv[6]; int ov[6];
#pragma unroll
    for (int c = 0; c < 6; c++) {
        const unsigned char* p = cand[c];
        bv[c] = p[(size_t)t * (size_t)(n[c] / SAMPLES)];
        wv[c] = ((const int*)p)[(size_t)t * (size_t)((n[c] / 4) / SAMPLES)];
        ov[c] = ((const int*)p)[2 * (t & 127) + 1];  // odd 32-bit words
    }
    const unsigned char pb = pm[(size_t)t * (8192 / SAMPLES)];
    const int pw = ((const int*)pm)[(size_t)t * ((8192 / 4) / SAMPLES)];

#pragma unroll
    for (int c = 0; c < 6; c++) {
        if (bv[c] > 1)                                   v_byte[c] = 1;
        if ((unsigned)wv[c] > 1u)                        v_w01[c]  = 1;
        if (wv[c] != 0 && wv[c] != 0x3F800000)           v_wf[c]   = 1;
        if (ov[c] != 0)                                  v_odd[c]  = 1;
    }
    if (pb > 1)                                          v_byte[6] = 1;
    if ((unsigned)pw > 1u)                               v_w01[6]  = 1;
    if (pw != 0 && pw != 0x3F800000)                     v_wf[6]   = 1;
    __syncthreads();

    if (t == 0) {
        for (int k = 0; k < 3; k++) {
            const int A = 2 * k, B = 2 * k + 1;
            // A buffer is a mask iff any of the "all values are bool-like"
            // tests has NO violations.
            const int maskA = (!v_w01[A]) || (!v_wf[A]) || (!v_byte[A]);
            const int maskB = (!v_w01[B]) || (!v_wf[B]) || (!v_byte[B]);
            const int swap = (maskA && !maskB) ? 1 : 0;  // default: A=ids
            const int idsI = swap ? B : A;
            const int mI   = swap ? A : B;
            g_cfg[k]     = swap;
            g_cfg[3 + k] = v_odd[idsI] ? 1 : 2;          // odd words all zero => int64
            g_cfg[6 + k] = ((!v_w01[mI]) || (!v_wf[mI])) ? 4 : 1;
        }
        g_cfg[9] = ((!v_w01[6]) || (!v_wf[6])) ? 4 : 1;
    }
}

__device__ __forceinline__ int read_mask(const unsigned char* m, int idx, int w) {
    return (w == 4) ? (((const int*)m)[idx] != 0) : (m[idx] != 0);
}

__global__ __launch_bounds__(128, 8) void patch_embed_kernel(
    const unsigned char* __restrict__ a1, const unsigned char* __restrict__ b1,
    const unsigned char* __restrict__ a2, const unsigned char* __restrict__ b2,
    const unsigned char* __restrict__ a3, const unsigned char* __restrict__ b3,
    const unsigned char* __restrict__ pmask,
    const float4* __restrict__ e1,
    const float4* __restrict__ e2,
    const float4* __restrict__ e3,
    float4* __restrict__ out)
{
    __shared__ const float4* ptrs[LTOT];

    const int patch = blockIdx.x;   // 0..8191
    const int t = threadIdx.x;      // 0..127

    if (t < LTOT) {
        const float4* p = nullptr;
        const int wp = g_cfg[9];
        if (read_mask(pmask, patch, wp)) {
            int k, j, nk;
            const unsigned char *pa, *pb;
            const float4* e;
            if (t < L1N)            { k = 0; j = t;             nk = L1N; pa = a1; pb = b1; e = e1; }
            else if (t < L1N + L2N) { k = 1; j = t - L1N;       nk = L2N; pa = a2; pb = b2; e = e2; }
            else                    { k = 2; j = t - L1N - L2N; nk = L3N; pa = a3; pb = b3; e = e3; }

            const int swap = g_cfg[k];
            const int s    = g_cfg[3 + k];
            const int wm   = g_cfg[6 + k];
            const unsigned char* ids = swap ? pb : pa;
            const unsigned char* msk = swap ? pa : pb;
            const int idx = patch * nk + j;
            if (read_mask(msk, idx, wm)) {
                const unsigned id = (unsigned)((const int*)ids)[idx * s] & 0xFFFFu;
                p = e + (size_t)id * DV;
            }
        }
        ptrs[t] = p;
    }
    __syncthreads();

    float4 acc = make_float4(0.f, 0.f, 0.f, 0.f);
#pragma unroll
    for (int i = 0; i < LTOT; i++) {
        const float4* p = ptrs[i];       // warp-uniform
        if (p) {
            const float4 v = __ldg(p + t);
            acc.x += v.x; acc.y += v.y; acc.z += v.z; acc.w += v.w;
        }
    }
    out[(size_t)patch * DV + t] = acc;
}

extern "C" void kernel_launch(void* const* d_in, const int* in_sizes, int n_in,
                              void* d_out, int out_size)
{
    const unsigned char *a1 = nullptr, *b1 = nullptr;
    const unsigned char *a2 = nullptr, *b2 = nullptr;
    const unsigned char *a3 = nullptr, *b3 = nullptr;
    const unsigned char *pm = nullptr;
    const float4* emb[3] = {nullptr, nullptr, nullptr};
    int ne = 0;

    for (int i = 0; i < n_in; i++) {
        const int sz = in_sizes[i];
        const unsigned char* p = (const unsigned char*)d_in[i];
        switch (sz) {
            case 33554432: if (ne < 3) emb[ne++] = (const float4*)p; break;
            case 8192:     pm = p; break;
            case 65536:    if (!a1) a1 = p; else b1 = p; break;
            case 57344:    if (!a2) a2 = p; else b2 = p; break;
            case 49152:    if (!a3) a3 = p; else b3 = p; break;
            default: break;
        }
    }

    probe_kernel<<<1, SAMPLES>>>(a1, b1, a2, b2, a3, b3, pm);
    patch_embed_kernel<<<NPATCH, 128>>>(a1, b1, a2, b2, a3, b3, pm,
                                        emb[0], emb[1], emb[2],
                                        (float4*)d_out);
}